// round 14
// baseline (speedup 1.0000x reference)
#include <cuda_runtime.h>
#include <math.h>

#define VSZ 20000
#define VTZ 20000
#define BQN 2000
#define DSD 300
#define DSP 320   // padded k-stride for src/tgt/q combined vectors (zero tail)
#define DCD 1024
#define TOPK 10

typedef unsigned long long u64;

// ---------------- scratch: static device globals ----------------
__device__ float g_h[(size_t)VSZ * DSD];
__device__ float g_pre[(size_t)VSZ * DSD];
__device__ float g_tmp[(size_t)VSZ * DSD];
__device__ float g_src[(size_t)VSZ * DSP];   // src_comb, stride 320, zero-padded
__device__ float g_tgt[(size_t)VTZ * DSP];   // tgt_comb, stride 320, zero-padded
__device__ float g_q[(size_t)BQN * DSP];     // queries,  stride 320, zero-padded
__device__ float g_qtmp[(size_t)BQN * DSD];
__device__ float g_mean[DSD];
__device__ float g_bwd[VTZ];

// ---------------- packed fp32x2 helpers (bit-identical IEEE fp32 per half) ----------------
__device__ __forceinline__ u64 pack2(float x, float y) {
    u64 r; asm("mov.b64 %0, {%1, %2};" : "=l"(r) : "f"(x), "f"(y)); return r;
}
__device__ __forceinline__ void fma2(u64& acc, u64 a, u64 b) {
    asm("fma.rn.f32x2 %0, %1, %2, %0;" : "+l"(acc) : "l"(a), "l"(b));
}
__device__ __forceinline__ float2 unpack2(u64 v) {
    float2 r; asm("mov.b64 {%0, %1}, %2;" : "=f"(r.x), "=f"(r.y) : "l"(v)); return r;
}

// ---------------- canary fallback ----------------
__global__ void fallback_fill_kernel(float* __restrict__ out, int n) {
    int i = blockIdx.x * 256 + threadIdx.x;
    if (i < n) out[i] = -30000.0f;
}

__device__ __forceinline__ int get_id(const int* __restrict__ idx, int r) {
    bool is64 = (idx[1] == 0) && (idx[3] == 0) && (idx[5] == 0) && (idx[7] == 0);
    int v = is64 ? idx[2 * r] : idx[r];
    return min(max(v, 0), VSZ - 1);
}

// ---------------- GEMM v2: C = tanh(A @ W^T + bias), 64x128 tile, FFMA2, double-buffered ----
// (unchanged from R12 — validated rel_err 0.0)
#define GEMM_SMEM 51200
__global__ void __launch_bounds__(128) gemm_tanh2_kernel(
    const float* __restrict__ Ain, int a_sel,
    const float* __restrict__ W, const float* __restrict__ bias,
    int c_sel, int M, int N, int K, int lda) {
    const float* A = (a_sel == 0) ? Ain : (const float*)g_h;
    float* C = (c_sel == 0) ? g_h : g_pre;
    extern __shared__ __align__(16) float sm[];
    float* AsB[2] = {sm, sm + 32 * 68};
    float* BsB[2] = {sm + 2 * 32 * 68, sm + 2 * 32 * 68 + 32 * 132};

    const int tid = threadIdx.x;
    const int row0 = blockIdx.y * 64, col0 = blockIdx.x * 128;
    const int m0 = (tid >> 4) << 3;
    const int n0 = (tid & 15) << 3;
    const int nch = (K + 31) / 32;

    u64 acc[8][4];
#pragma unroll
    for (int i = 0; i < 8; i++)
#pragma unroll
        for (int jp = 0; jp < 4; jp++) acc[i][jp] = 0ull;

    float4 pa[4], pb[8];
#pragma unroll
    for (int cc = 0; cc < 4; cc++) {
        int j = cc * 128 + tid, m = j >> 3, kq = j & 7;
        int gr = row0 + m, gk = kq * 4;
        pa[cc] = (gr < M && gk < K) ? *(const float4*)&A[(size_t)gr * lda + gk]
                                    : make_float4(0.f, 0.f, 0.f, 0.f);
    }
#pragma unroll
    for (int cc = 0; cc < 8; cc++) {
        int j = cc * 128 + tid, n = j >> 3, kq = j & 7;
        int gc = col0 + n, gk = kq * 4;
        pb[cc] = (gc < N && gk < K) ? *(const float4*)&W[(size_t)gc * K + gk]
                                    : make_float4(0.f, 0.f, 0.f, 0.f);
    }
    {
        float* Ax = AsB[0];
        float* Bx = BsB[0];
#pragma unroll
        for (int cc = 0; cc < 4; cc++) {
            int j = cc * 128 + tid, m = j >> 3, kq = j & 7;
            Ax[(kq * 4 + 0) * 68 + m] = pa[cc].x;
            Ax[(kq * 4 + 1) * 68 + m] = pa[cc].y;
            Ax[(kq * 4 + 2) * 68 + m] = pa[cc].z;
            Ax[(kq * 4 + 3) * 68 + m] = pa[cc].w;
        }
#pragma unroll
        for (int cc = 0; cc < 8; cc++) {
            int j = cc * 128 + tid, n = j >> 3, kq = j & 7;
            Bx[(kq * 4 + 0) * 132 + n] = pb[cc].x;
            Bx[(kq * 4 + 1) * 132 + n] = pb[cc].y;
            Bx[(kq * 4 + 2) * 132 + n] = pb[cc].z;
            Bx[(kq * 4 + 3) * 132 + n] = pb[cc].w;
        }
    }
    __syncthreads();

    for (int c = 0; c < nch; c++) {
        if (c + 1 < nch) {
            const int kb = (c + 1) * 32;
#pragma unroll
            for (int cc = 0; cc < 4; cc++) {
                int j = cc * 128 + tid, m = j >> 3, kq = j & 7;
                int gr = row0 + m, gk = kb + kq * 4;
                pa[cc] = (gr < M && gk < K) ? *(const float4*)&A[(size_t)gr * lda + gk]
                                            : make_float4(0.f, 0.f, 0.f, 0.f);
            }
#pragma unroll
            for (int cc = 0; cc < 8; cc++) {
                int j = cc * 128 + tid, n = j >> 3, kq = j & 7;
                int gc = col0 + n, gk = kb + kq * 4;
                pb[cc] = (gc < N && gk < K) ? *(const float4*)&W[(size_t)gc * K + gk]
                                            : make_float4(0.f, 0.f, 0.f, 0.f);
            }
        }
        const float* Ab = AsB[c & 1];
        const float* Bb = BsB[c & 1];
#pragma unroll 4
        for (int k = 0; k < 32; k++) {
            float4 a0 = *(const float4*)&Ab[k * 68 + m0];
            float4 a1 = *(const float4*)&Ab[k * 68 + m0 + 4];
            float4 b0 = *(const float4*)&Bb[k * 132 + n0];
            float4 b1 = *(const float4*)&Bb[k * 132 + n0 + 4];
            u64 bp0 = pack2(b0.x, b0.y), bp1 = pack2(b0.z, b0.w);
            u64 bp2 = pack2(b1.x, b1.y), bp3 = pack2(b1.z, b1.w);
            float am[8] = {a0.x, a0.y, a0.z, a0.w, a1.x, a1.y, a1.z, a1.w};
#pragma unroll
            for (int i = 0; i < 8; i++) {
                u64 a2 = pack2(am[i], am[i]);
                fma2(acc[i][0], a2, bp0);
                fma2(acc[i][1], a2, bp1);
                fma2(acc[i][2], a2, bp2);
                fma2(acc[i][3], a2, bp3);
            }
        }
        __syncthreads();
        if (c + 1 < nch) {
            float* An = AsB[(c + 1) & 1];
            float* Bn = BsB[(c + 1) & 1];
#pragma unroll
            for (int cc = 0; cc < 4; cc++) {
                int j = cc * 128 + tid, m = j >> 3, kq = j & 7;
                An[(kq * 4 + 0) * 68 + m] = pa[cc].x;
                An[(kq * 4 + 1) * 68 + m] = pa[cc].y;
                An[(kq * 4 + 2) * 68 + m] = pa[cc].z;
                An[(kq * 4 + 3) * 68 + m] = pa[cc].w;
            }
#pragma unroll
            for (int cc = 0; cc < 8; cc++) {
                int j = cc * 128 + tid, n = j >> 3, kq = j & 7;
                Bn[(kq * 4 + 0) * 132 + n] = pb[cc].x;
                Bn[(kq * 4 + 1) * 132 + n] = pb[cc].y;
                Bn[(kq * 4 + 2) * 132 + n] = pb[cc].z;
                Bn[(kq * 4 + 3) * 132 + n] = pb[cc].w;
            }
            __syncthreads();
        }
    }
#pragma unroll
    for (int i = 0; i < 8; i++) {
        int gr = row0 + m0 + i;
        if (gr >= M) continue;
#pragma unroll
        for (int jp = 0; jp < 4; jp++) {
            float2 v = unpack2(acc[i][jp]);
            int gc = col0 + n0 + jp * 2;
            if (gc < N) C[(size_t)gr * N + gc] = tanhf(v.x + bias[gc]);
            if (gc + 1 < N) C[(size_t)gr * N + gc + 1] = tanhf(v.y + bias[gc + 1]);
        }
    }
}

// ---------------- row L2 normalize (unchanged) ----------------
__global__ void l2rows_kernel(const int* __restrict__ idx, int dst_sel, int n) {
    float* out = dst_sel ? g_qtmp : g_tmp;
    int r = blockIdx.x;
    if (r >= n) return;
    int sr = idx ? get_id(idx, r) : r;
    const float* src = g_pre + (size_t)sr * DSD;
    float s = 0.f;
    for (int i = threadIdx.x; i < DSD; i += 128) {
        float x = src[i];
        s += x * x;
    }
    __shared__ float red[4];
    __shared__ float s_inv;
    int lane = threadIdx.x & 31, w = threadIdx.x >> 5;
#pragma unroll
    for (int o = 16; o; o >>= 1) s += __shfl_xor_sync(0xffffffffu, s, o);
    if (lane == 0) red[w] = s;
    __syncthreads();
    if (threadIdx.x == 0) s_inv = 1.0f / sqrtf(red[0] + red[1] + red[2] + red[3]);
    __syncthreads();
    float inv = s_inv;
    for (int i = threadIdx.x; i < DSD; i += 128) out[(size_t)r * DSD + i] = src[i] * inv;
}

// ---------------- column mean (unchanged) ----------------
__global__ void colmean_kernel(int src_sel, int n, float inv_n) {
    const float* Y = src_sel ? g_qtmp : g_tmp;
    int c = blockIdx.x;
    float s = 0.f;
    for (int r = threadIdx.x; r < n; r += 128) s += Y[(size_t)r * DSD + c];
    __shared__ float red[4];
    int lane = threadIdx.x & 31, w = threadIdx.x >> 5;
#pragma unroll
    for (int o = 16; o; o >>= 1) s += __shfl_xor_sync(0xffffffffu, s, o);
    if (lane == 0) red[w] = s;
    __syncthreads();
    if (threadIdx.x == 0) g_mean[c] = (red[0] + red[1] + red[2] + red[3]) * inv_n;
}

// ---- combine: writes stride-DSP output with zero-padded tail (unchanged) ----
__global__ void combine_kernel(const float* __restrict__ base_tab, const int* __restrict__ bidx,
                               int y_sel, const float* __restrict__ w, int dst_sel, int n) {
    const float* Y = y_sel ? g_qtmp : g_tmp;
    float* out = (dst_sel == 0) ? g_src : (dst_sel == 1) ? g_tgt : g_q;
    int r = blockIdx.x;
    if (r >= n) return;
    int br = bidx ? get_id(bidx, r) : r;
    const float* b = base_tab + (size_t)br * DSD;
    const float* y = Y + (size_t)r * DSD;
    float sb = 0.f, sc = 0.f;
    for (int i = threadIdx.x; i < DSD; i += 128) {
        float vb = b[i];
        sb += vb * vb;
        float vc = y[i] - g_mean[i];
        sc += vc * vc;
    }
    int lane = threadIdx.x & 31, wrp = threadIdx.x >> 5;
#pragma unroll
    for (int o = 16; o; o >>= 1) {
        sb += __shfl_xor_sync(0xffffffffu, sb, o);
        sc += __shfl_xor_sync(0xffffffffu, sc, o);
    }
    __shared__ float rb[4], rc[4];
    __shared__ float ivb_s, ivc_s;
    if (lane == 0) { rb[wrp] = sb; rc[wrp] = sc; }
    __syncthreads();
    if (threadIdx.x == 0) {
        ivb_s = 1.0f / sqrtf(rb[0] + rb[1] + rb[2] + rb[3]);
        ivc_s = 1.0f / sqrtf(rc[0] + rc[1] + rc[2] + rc[3]);
    }
    __syncthreads();
    float ib = ivb_s, ic = ivc_s;
    for (int i = threadIdx.x; i < DSP; i += 128) {
        float v = 0.f;
        if (i < DSD) v = b[i] * ib + w[i] * (y[i] - g_mean[i]) * ic;
        out[(size_t)r * DSP + i] = v;
    }
}

// ---------------- bwd v4: 64x128 tile, A duplicated in smem ({a,a} via LDS.64),
// B pairs native (LDS.128 -> u64x2), ZERO packs, double-buffered, 67.6KB -> 3 blocks/SM cap.
// Sequential k per accumulator half => g_bwd bit-identical to R11/R12.
#define BWD_SMEM (4 * 32 * 132 * 4)   // 67584 B
__global__ void __launch_bounds__(128) bwd_kernel() {
    extern __shared__ __align__(16) float sm[];
    float* A2B[2] = {sm, sm + 32 * 132};                 // duplicated A: [k][2m], stride 132
    float* BsB[2] = {sm + 2 * 32 * 132, sm + 3 * 32 * 132};  // B: [k][n], stride 132
    float* scores = sm;   // 64*132 = 8448 floats == A2 region exactly; dead during scan
    float* cand = sm;

    const int tid = threadIdx.x;
    const int r0 = blockIdx.x * 64;
    const int m0 = (tid >> 4) << 3;   // 0..56
    const int n0 = (tid & 15) << 3;   // 0..120
    const int srow = tid & 63;
    const int part = tid >> 6;

    float top[TOPK];
#pragma unroll
    for (int i = 0; i < TOPK; i++) top[i] = -3.0e38f;

    float4 pa[4], pb[8];

    for (int s0 = 0; s0 < VSZ; s0 += 128) {
        u64 acc[8][4];
#pragma unroll
        for (int i = 0; i < 8; i++)
#pragma unroll
            for (int jp = 0; jp < 4; jp++) acc[i][jp] = 0ull;

        // LDG chunk 0 (A and B) into regs
#pragma unroll
        for (int cc = 0; cc < 4; cc++) {
            int j = cc * 128 + tid, m = j >> 3, kq = j & 7;
            int gr = r0 + m;
            pa[cc] = (gr < VTZ) ? *(const float4*)&g_tgt[(size_t)gr * DSP + kq * 4]
                                : make_float4(0.f, 0.f, 0.f, 0.f);
        }
#pragma unroll
        for (int cc = 0; cc < 8; cc++) {
            int j = cc * 128 + tid, n = j >> 3, kq = j & 7;
            int gs = s0 + n;
            pb[cc] = (gs < VSZ) ? *(const float4*)&g_src[(size_t)gs * DSP + kq * 4]
                                : make_float4(0.f, 0.f, 0.f, 0.f);
        }
        __syncthreads();  // previous s0's scan reads complete before smem overwrite
        {
            float* A2 = A2B[0];
            float* B = BsB[0];
#pragma unroll
            for (int cc = 0; cc < 4; cc++) {
                int j = cc * 128 + tid, m = j >> 3, kq = j & 7;
                float vv[4] = {pa[cc].x, pa[cc].y, pa[cc].z, pa[cc].w};
#pragma unroll
                for (int c2 = 0; c2 < 4; c2++) {
                    A2[(kq * 4 + c2) * 132 + 2 * m] = vv[c2];
                    A2[(kq * 4 + c2) * 132 + 2 * m + 1] = vv[c2];
                }
            }
#pragma unroll
            for (int cc = 0; cc < 8; cc++) {
                int j = cc * 128 + tid, n = j >> 3, kq = j & 7;
                B[(kq * 4 + 0) * 132 + n] = pb[cc].x;
                B[(kq * 4 + 1) * 132 + n] = pb[cc].y;
                B[(kq * 4 + 2) * 132 + n] = pb[cc].z;
                B[(kq * 4 + 3) * 132 + n] = pb[cc].w;
            }
        }
        __syncthreads();

        for (int c = 0; c < 10; c++) {
            if (c < 9) {
                const int kb = (c + 1) * 32;
#pragma unroll
                for (int cc = 0; cc < 4; cc++) {
                    int j = cc * 128 + tid, m = j >> 3, kq = j & 7;
                    int gr = r0 + m;
                    pa[cc] = (gr < VTZ) ? *(const float4*)&g_tgt[(size_t)gr * DSP + kb + kq * 4]
                                        : make_float4(0.f, 0.f, 0.f, 0.f);
                }
#pragma unroll
                for (int cc = 0; cc < 8; cc++) {
                    int j = cc * 128 + tid, n = j >> 3, kq = j & 7;
                    int gs = s0 + n;
                    pb[cc] = (gs < VSZ) ? *(const float4*)&g_src[(size_t)gs * DSP + kb + kq * 4]
                                        : make_float4(0.f, 0.f, 0.f, 0.f);
                }
            }
            const float* A2 = A2B[c & 1];
            const float* B = BsB[c & 1];
#pragma unroll 4
            for (int k = 0; k < 32; k++) {
                // B pairs: {b[n0+0],b[n0+1]},{b[n0+2],b[n0+3]},... native LDS.128
                ulonglong2 bb01 = *(const ulonglong2*)&B[k * 132 + n0];
                ulonglong2 bb23 = *(const ulonglong2*)&B[k * 132 + n0 + 4];
                const float* Ar = &A2[k * 132 + 2 * m0];
#pragma unroll
                for (int i = 0; i < 8; i++) {
                    u64 a2 = *(const u64*)&Ar[2 * i];   // {a,a} duplicated, LDS.64
                    fma2(acc[i][0], a2, bb01.x);
                    fma2(acc[i][1], a2, bb01.y);
                    fma2(acc[i][2], a2, bb23.x);
                    fma2(acc[i][3], a2, bb23.y);
                }
            }
            __syncthreads();
            if (c < 9) {
                float* A2n = A2B[(c + 1) & 1];
                float* Bn = BsB[(c + 1) & 1];
#pragma unroll
                for (int cc = 0; cc < 4; cc++) {
                    int j = cc * 128 + tid, m = j >> 3, kq = j & 7;
                    float vv[4] = {pa[cc].x, pa[cc].y, pa[cc].z, pa[cc].w};
#pragma unroll
                    for (int c2 = 0; c2 < 4; c2++) {
                        A2n[(kq * 4 + c2) * 132 + 2 * m] = vv[c2];
                        A2n[(kq * 4 + c2) * 132 + 2 * m + 1] = vv[c2];
                    }
                }
#pragma unroll
                for (int cc = 0; cc < 8; cc++) {
                    int j = cc * 128 + tid, n = j >> 3, kq = j & 7;
                    Bn[(kq * 4 + 0) * 132 + n] = pb[cc].x;
                    Bn[(kq * 4 + 1) * 132 + n] = pb[cc].y;
                    Bn[(kq * 4 + 2) * 132 + n] = pb[cc].z;
                    Bn[(kq * 4 + 3) * 132 + n] = pb[cc].w;
                }
                __syncthreads();
            }
        }
        // stage scores over dead A2 region
#pragma unroll
        for (int i = 0; i < 8; i++)
#pragma unroll
            for (int jp = 0; jp < 4; jp++) {
                float2 v = unpack2(acc[i][jp]);
                *(float2*)&scores[(m0 + i) * 132 + n0 + jp * 2] = v;
            }
        __syncthreads();
        // per-thread partial top-10 over 64 columns
#pragma unroll 8
        for (int cc = 0; cc < 64; cc++) {
            int n = part * 64 + cc;
            int gs = s0 + n;
            float v = scores[srow * 132 + n];
            if (gs < VSZ && v > top[TOPK - 1]) {
#pragma unroll
                for (int i = 0; i < TOPK; i++) {
                    if (v > top[i]) { float t = top[i]; top[i] = v; v = t; }
                }
            }
        }
        // no trailing sync: next s0's pre-STS sync covers the scan reads
    }
    __syncthreads();
#pragma unroll
    for (int i = 0; i < TOPK; i++) cand[srow * 20 + part * 10 + i] = top[i];
    __syncthreads();
    if (tid < 64 && r0 + tid < VTZ) {
        float* c = cand + tid * 20;
        float sum = 0.f;
        for (int j = 0; j < TOPK; j++) {
            float mx = -3.0e38f;
            int mi = 0;
            for (int i = 0; i < 20; i++) {
                float v = c[i];
                if (v > mx) { mx = v; mi = i; }
            }
            sum += mx;
            c[mi] = -3.0e38f;
        }
        g_bwd[r0 + tid] = sum * (1.0f / TOPK);
    }
}

// ---------------- final: UNTOUCHED numerics (R9/R11/R12-passing) ----------------
__global__ void final_kernel(float* __restrict__ out) {
    __shared__ __align__(16) float Aq[DSD * 16];
    __shared__ __align__(16) float U[20 * 256];
    const int tid = threadIdx.x;
    const int b0 = blockIdx.x * 16;

    for (int i = tid; i < 16 * DSD; i += 256) {
        int m = i / DSD, k = i - m * DSD;
        Aq[k * 16 + m] = g_q[(size_t)(b0 + m) * DSP + k];
    }
    const int rowg = tid >> 6;
    const int colg = tid & 63;
    const int srow = tid >> 4;
    const int scol0 = (tid & 15) * 16;
    float tv[TOPK];
    int ti[TOPK];
#pragma unroll
    for (int i = 0; i < TOPK; i++) { tv[i] = -3.0e38f; ti[i] = 0x7fffffff; }
    __syncthreads();

    for (int t0 = 0; t0 < VTZ; t0 += 256) {
        float sum[4][4], comp[4][4];
#pragma unroll
        for (int i = 0; i < 4; i++)
#pragma unroll
            for (int j = 0; j < 4; j++) { sum[i][j] = 0.f; comp[i][j] = 0.f; }

        for (int k0 = 0; k0 < DSD; k0 += 20) {
            for (int i = tid; i < 256 * 20; i += 256) {
                int n = i / 20, k = i - n * 20;
                int gt = t0 + n;
                U[k * 256 + n] = (gt < VTZ) ? g_tgt[(size_t)gt * DSP + k0 + k] : 0.f;
            }
            __syncthreads();
            float a0[4][4], a1[4][4];
#pragma unroll
            for (int i = 0; i < 4; i++)
#pragma unroll
                for (int j = 0; j < 4; j++) { a0[i][j] = 0.f; a1[i][j] = 0.f; }
#pragma unroll 5
            for (int k = 0; k < 20; k += 2) {
                float4 xa = *(const float4*)&Aq[(k0 + k) * 16 + rowg * 4];
                float4 xb = *(const float4*)&U[k * 256 + colg * 4];
                float4 ya = *(const float4*)&Aq[(k0 + k + 1) * 16 + rowg * 4];
                float4 yb = *(const float4*)&U[(k + 1) * 256 + colg * 4];
                float av0[4] = {xa.x, xa.y, xa.z, xa.w};
                float bv0[4] = {xb.x, xb.y, xb.z, xb.w};
                float av1[4] = {ya.x, ya.y, ya.z, ya.w};
                float bv1[4] = {yb.x, yb.y, yb.z, yb.w};
#pragma unroll
                for (int i = 0; i < 4; i++)
#pragma unroll
                    for (int j = 0; j < 4; j++) {
                        a0[i][j] = fmaf(av0[i], bv0[j], a0[i][j]);
                        a1[i][j] = fmaf(av1[i], bv1[j], a1[i][j]);
                    }
            }
#pragma unroll
            for (int i = 0; i < 4; i++)
#pragma unroll
                for (int j = 0; j < 4; j++) {
                    float x = a0[i][j] + a1[i][j];
                    float t = sum[i][j] + x;
                    float e = (sum[i][j] - t) + x;
                    comp[i][j] += e;
                    sum[i][j] = t;
                }
            __syncthreads();
        }
#pragma unroll
        for (int j = 0; j < 4; j++) {
            int gt = t0 + colg * 4 + j;
            float bw = (gt < VTZ) ? g_bwd[gt] : 0.f;
#pragma unroll
            for (int i = 0; i < 4; i++) {
                float sim = sum[i][j] + comp[i][j];
                U[(rowg * 4 + i) * 260 + colg * 4 + j] = 2.f * sim - bw;
            }
        }
        __syncthreads();
#pragma unroll
        for (int c = 0; c < 16; c++) {
            int gt = t0 + scol0 + c;
            if (gt < VTZ) {
                float v = U[srow * 260 + scol0 + c];
                if (v > tv[TOPK - 1]) {
                    int id = gt;
#pragma unroll
                    for (int i = 0; i < TOPK; i++) {
                        if (v > tv[i]) {
                            float t = tv[i]; tv[i] = v; v = t;
                            int tt = ti[i]; ti[i] = id; id = tt;
                        }
                    }
                }
            }
        }
        __syncthreads();
    }
    float* cv = U;
    int* ci = (int*)(U + 16 * 160);
    const int part = tid & 15;
#pragma unroll
    for (int i = 0; i < TOPK; i++) {
        cv[srow * 160 + part * 10 + i] = tv[i];
        ci[srow * 160 + part * 10 + i] = ti[i];
    }
    __syncthreads();
    if (tid < 16) {
        float* v = cv + tid * 160;
        int* id = ci + tid * 160;
        int b = b0 + tid;
        for (int j = 0; j < TOPK; j++) {
            float mx = -3.0e38f;
            int mi = -1, midx = 0x7fffffff;
            for (int i = 0; i < 160; i++) {
                float vv = v[i];
                int vi = id[i];
                if (vv > mx || (vv == mx && vi < midx)) { mx = vv; mi = i; midx = vi; }
            }
            out[b * TOPK + j] = (float)midx;
            v[mi] = -3.0e38f;
        }
    }
}

// ---------------- launch ----------------
extern "C" void kernel_launch(void* const* d_in, const int* in_sizes, int n_in,
                              void* d_out, int out_size) {
    const int* sid;
    const int* cid;
    const float *sst, *stt, *cst, *ctt, *W1, *b1, *W2, *b2, *W3, *b3, *W4, *b4, *w1, *w2;

    long s0 = (n_in >= 16) ? (long)in_sizes[0] : 0;
    bool alphabetical = (s0 == 307200L) || (s0 == 307200L * 4L);

    if (alphabetical) {
        W1 = (const float*)d_in[0];  W2 = (const float*)d_in[1];
        W3 = (const float*)d_in[2];  W4 = (const float*)d_in[3];
        b1 = (const float*)d_in[4];  b2 = (const float*)d_in[5];
        b3 = (const float*)d_in[6];  b4 = (const float*)d_in[7];
        cid = (const int*)d_in[8];
        cst = (const float*)d_in[9];
        ctt = (const float*)d_in[10];
        sid = (const int*)d_in[11];
        sst = (const float*)d_in[12];
        stt = (const float*)d_in[13];
        w1 = (const float*)d_in[14]; w2 = (const float*)d_in[15];
    } else {
        sid = (const int*)d_in[0];
        cid = (const int*)d_in[1];
        sst = (const float*)d_in[2];
        stt = (const float*)d_in[3];
        cst = (const float*)d_in[4];
        ctt = (const float*)d_in[5];
        W1 = (const float*)d_in[6];  b1 = (const float*)d_in[7];
        W2 = (const float*)d_in[8];  b2 = (const float*)d_in[9];
        W3 = (const float*)d_in[10]; b3 = (const float*)d_in[11];
        W4 = (const float*)d_in[12]; b4 = (const float*)d_in[13];
        w1 = (const float*)d_in[14]; w2 = (const float*)d_in[15];
    }
    float* out = (float*)d_out;

    cudaFuncSetAttribute(bwd_kernel, cudaFuncAttributeMaxDynamicSharedMemorySize, BWD_SMEM);
    cudaFuncSetAttribute(gemm_tanh2_kernel, cudaFuncAttributeMaxDynamicSharedMemorySize, GEMM_SMEM);

    // canary FIRST
    fallback_fill_kernel<<<(BQN * TOPK + 255) / 256, 256>>>(out, BQN * TOPK);

    dim3 gg2((DSD + 127) / 128, (VSZ + 63) / 64);  // (3, 313)

    // source-context MLP
    gemm_tanh2_kernel<<<gg2, 128, GEMM_SMEM>>>(cst, 0, W1, b1, 0, VSZ, DSD, DCD, DCD);
    gemm_tanh2_kernel<<<gg2, 128, GEMM_SMEM>>>(nullptr, 1, W3, b3, 1, VSZ, DSD, DSD, DSD);
    l2rows_kernel<<<VSZ, 128>>>(nullptr, 0, VSZ);
    colmean_kernel<<<DSD, 128>>>(0, VSZ, 1.0f / VSZ);
    combine_kernel<<<VSZ, 128>>>(sst, nullptr, 0, w1, 0, VSZ);

    // query path
    l2rows_kernel<<<BQN, 128>>>(cid, 1, BQN);
    colmean_kernel<<<DSD, 128>>>(1, BQN, 1.0f / BQN);
    combine_kernel<<<BQN, 128>>>(sst, sid, 1, w1, 2, BQN);

    // target-context MLP
    gemm_tanh2_kernel<<<gg2, 128, GEMM_SMEM>>>(ctt, 0, W2, b2, 0, VTZ, DSD, DCD, DCD);
    gemm_tanh2_kernel<<<gg2, 128, GEMM_SMEM>>>(nullptr, 1, W4, b4, 1, VTZ, DSD, DSD, DSD);
    l2rows_kernel<<<VTZ, 128>>>(nullptr, 0, VTZ);
    colmean_kernel<<<DSD, 128>>>(0, VTZ, 1.0f / VTZ);
    combine_kernel<<<VTZ, 128>>>(stt, nullptr, 0, w2, 1, VTZ);

    // backward CSLS term (v4: pack-free FFMA2, 3-blocks/SM occupancy)
    bwd_kernel<<<(VTZ + 63) / 64, 128, BWD_SMEM>>>();

    // final scores + top-k indices
    final_kernel<<<BQN / 16, 256>>>(out);
}

// round 15
// speedup vs baseline: 1.0956x; 1.0956x over previous
#include <cuda_runtime.h>
#include <math.h>

#define VSZ 20000
#define VTZ 20000
#define BQN 2000
#define DSD 300
#define DSP 320   // padded k-stride for src/tgt/q combined vectors (zero tail)
#define DCD 1024
#define TOPK 10

typedef unsigned long long u64;

// ---------------- scratch: static device globals ----------------
__device__ float g_h[(size_t)VSZ * DSD];
__device__ float g_pre[(size_t)VSZ * DSD];
__device__ float g_tmp[(size_t)VSZ * DSD];
__device__ float g_src[(size_t)VSZ * DSP];   // src_comb, stride 320, zero-padded
__device__ float g_tgt[(size_t)VTZ * DSP];   // tgt_comb, stride 320, zero-padded
__device__ float g_q[(size_t)BQN * DSP];     // queries,  stride 320, zero-padded
__device__ float g_qtmp[(size_t)BQN * DSD];
__device__ float g_mean[DSD];
__device__ float g_bwd[VTZ];

// ---------------- packed fp32x2 helpers (bit-identical IEEE fp32 per half) ----------------
__device__ __forceinline__ u64 pack2(float x, float y) {
    u64 r; asm("mov.b64 %0, {%1, %2};" : "=l"(r) : "f"(x), "f"(y)); return r;
}
__device__ __forceinline__ void fma2(u64& acc, u64 a, u64 b) {
    asm("fma.rn.f32x2 %0, %1, %2, %0;" : "+l"(acc) : "l"(a), "l"(b));
}
__device__ __forceinline__ float2 unpack2(u64 v) {
    float2 r; asm("mov.b64 {%0, %1}, %2;" : "=f"(r.x), "=f"(r.y) : "l"(v)); return r;
}

// ---------------- canary fallback ----------------
__global__ void fallback_fill_kernel(float* __restrict__ out, int n) {
    int i = blockIdx.x * 256 + threadIdx.x;
    if (i < n) out[i] = -30000.0f;
}

__device__ __forceinline__ int get_id(const int* __restrict__ idx, int r) {
    bool is64 = (idx[1] == 0) && (idx[3] == 0) && (idx[5] == 0) && (idx[7] == 0);
    int v = is64 ? idx[2 * r] : idx[r];
    return min(max(v, 0), VSZ - 1);
}

// ---------------- GEMM v2: C = tanh(A @ W^T + bias), 64x128 tile, FFMA2, double-buffered ----
// (R12-validated, rel_err 0.0)
#define GEMM_SMEM 51200
__global__ void __launch_bounds__(128) gemm_tanh2_kernel(
    const float* __restrict__ Ain, int a_sel,
    const float* __restrict__ W, const float* __restrict__ bias,
    int c_sel, int M, int N, int K, int lda) {
    const float* A = (a_sel == 0) ? Ain : (const float*)g_h;
    float* C = (c_sel == 0) ? g_h : g_pre;
    extern __shared__ __align__(16) float sm[];
    float* AsB[2] = {sm, sm + 32 * 68};
    float* BsB[2] = {sm + 2 * 32 * 68, sm + 2 * 32 * 68 + 32 * 132};

    const int tid = threadIdx.x;
    const int row0 = blockIdx.y * 64, col0 = blockIdx.x * 128;
    const int m0 = (tid >> 4) << 3;
    const int n0 = (tid & 15) << 3;
    const int nch = (K + 31) / 32;

    u64 acc[8][4];
#pragma unroll
    for (int i = 0; i < 8; i++)
#pragma unroll
        for (int jp = 0; jp < 4; jp++) acc[i][jp] = 0ull;

    float4 pa[4], pb[8];
#pragma unroll
    for (int cc = 0; cc < 4; cc++) {
        int j = cc * 128 + tid, m = j >> 3, kq = j & 7;
        int gr = row0 + m, gk = kq * 4;
        pa[cc] = (gr < M && gk < K) ? *(const float4*)&A[(size_t)gr * lda + gk]
                                    : make_float4(0.f, 0.f, 0.f, 0.f);
    }
#pragma unroll
    for (int cc = 0; cc < 8; cc++) {
        int j = cc * 128 + tid, n = j >> 3, kq = j & 7;
        int gc = col0 + n, gk = kq * 4;
        pb[cc] = (gc < N && gk < K) ? *(const float4*)&W[(size_t)gc * K + gk]
                                    : make_float4(0.f, 0.f, 0.f, 0.f);
    }
    {
        float* Ax = AsB[0];
        float* Bx = BsB[0];
#pragma unroll
        for (int cc = 0; cc < 4; cc++) {
            int j = cc * 128 + tid, m = j >> 3, kq = j & 7;
            Ax[(kq * 4 + 0) * 68 + m] = pa[cc].x;
            Ax[(kq * 4 + 1) * 68 + m] = pa[cc].y;
            Ax[(kq * 4 + 2) * 68 + m] = pa[cc].z;
            Ax[(kq * 4 + 3) * 68 + m] = pa[cc].w;
        }
#pragma unroll
        for (int cc = 0; cc < 8; cc++) {
            int j = cc * 128 + tid, n = j >> 3, kq = j & 7;
            Bx[(kq * 4 + 0) * 132 + n] = pb[cc].x;
            Bx[(kq * 4 + 1) * 132 + n] = pb[cc].y;
            Bx[(kq * 4 + 2) * 132 + n] = pb[cc].z;
            Bx[(kq * 4 + 3) * 132 + n] = pb[cc].w;
        }
    }
    __syncthreads();

    for (int c = 0; c < nch; c++) {
        if (c + 1 < nch) {
            const int kb = (c + 1) * 32;
#pragma unroll
            for (int cc = 0; cc < 4; cc++) {
                int j = cc * 128 + tid, m = j >> 3, kq = j & 7;
                int gr = row0 + m, gk = kb + kq * 4;
                pa[cc] = (gr < M && gk < K) ? *(const float4*)&A[(size_t)gr * lda + gk]
                                            : make_float4(0.f, 0.f, 0.f, 0.f);
            }
#pragma unroll
            for (int cc = 0; cc < 8; cc++) {
                int j = cc * 128 + tid, n = j >> 3, kq = j & 7;
                int gc = col0 + n, gk = kb + kq * 4;
                pb[cc] = (gc < N && gk < K) ? *(const float4*)&W[(size_t)gc * K + gk]
                                            : make_float4(0.f, 0.f, 0.f, 0.f);
            }
        }
        const float* Ab = AsB[c & 1];
        const float* Bb = BsB[c & 1];
#pragma unroll 4
        for (int k = 0; k < 32; k++) {
            float4 a0 = *(const float4*)&Ab[k * 68 + m0];
            float4 a1 = *(const float4*)&Ab[k * 68 + m0 + 4];
            float4 b0 = *(const float4*)&Bb[k * 132 + n0];
            float4 b1 = *(const float4*)&Bb[k * 132 + n0 + 4];
            u64 bp0 = pack2(b0.x, b0.y), bp1 = pack2(b0.z, b0.w);
            u64 bp2 = pack2(b1.x, b1.y), bp3 = pack2(b1.z, b1.w);
            float am[8] = {a0.x, a0.y, a0.z, a0.w, a1.x, a1.y, a1.z, a1.w};
#pragma unroll
            for (int i = 0; i < 8; i++) {
                u64 a2 = pack2(am[i], am[i]);
                fma2(acc[i][0], a2, bp0);
                fma2(acc[i][1], a2, bp1);
                fma2(acc[i][2], a2, bp2);
                fma2(acc[i][3], a2, bp3);
            }
        }
        __syncthreads();
        if (c + 1 < nch) {
            float* An = AsB[(c + 1) & 1];
            float* Bn = BsB[(c + 1) & 1];
#pragma unroll
            for (int cc = 0; cc < 4; cc++) {
                int j = cc * 128 + tid, m = j >> 3, kq = j & 7;
                An[(kq * 4 + 0) * 68 + m] = pa[cc].x;
                An[(kq * 4 + 1) * 68 + m] = pa[cc].y;
                An[(kq * 4 + 2) * 68 + m] = pa[cc].z;
                An[(kq * 4 + 3) * 68 + m] = pa[cc].w;
            }
#pragma unroll
            for (int cc = 0; cc < 8; cc++) {
                int j = cc * 128 + tid, n = j >> 3, kq = j & 7;
                Bn[(kq * 4 + 0) * 132 + n] = pb[cc].x;
                Bn[(kq * 4 + 1) * 132 + n] = pb[cc].y;
                Bn[(kq * 4 + 2) * 132 + n] = pb[cc].z;
                Bn[(kq * 4 + 3) * 132 + n] = pb[cc].w;
            }
            __syncthreads();
        }
    }
#pragma unroll
    for (int i = 0; i < 8; i++) {
        int gr = row0 + m0 + i;
        if (gr >= M) continue;
#pragma unroll
        for (int jp = 0; jp < 4; jp++) {
            float2 v = unpack2(acc[i][jp]);
            int gc = col0 + n0 + jp * 2;
            if (gc < N) C[(size_t)gr * N + gc] = tanhf(v.x + bias[gc]);
            if (gc + 1 < N) C[(size_t)gr * N + gc + 1] = tanhf(v.y + bias[gc + 1]);
        }
    }
}

// ---------------- row L2 normalize (unchanged) ----------------
__global__ void l2rows_kernel(const int* __restrict__ idx, int dst_sel, int n) {
    float* out = dst_sel ? g_qtmp : g_tmp;
    int r = blockIdx.x;
    if (r >= n) return;
    int sr = idx ? get_id(idx, r) : r;
    const float* src = g_pre + (size_t)sr * DSD;
    float s = 0.f;
    for (int i = threadIdx.x; i < DSD; i += 128) {
        float x = src[i];
        s += x * x;
    }
    __shared__ float red[4];
    __shared__ float s_inv;
    int lane = threadIdx.x & 31, w = threadIdx.x >> 5;
#pragma unroll
    for (int o = 16; o; o >>= 1) s += __shfl_xor_sync(0xffffffffu, s, o);
    if (lane == 0) red[w] = s;
    __syncthreads();
    if (threadIdx.x == 0) s_inv = 1.0f / sqrtf(red[0] + red[1] + red[2] + red[3]);
    __syncthreads();
    float inv = s_inv;
    for (int i = threadIdx.x; i < DSD; i += 128) out[(size_t)r * DSD + i] = src[i] * inv;
}

// ---------------- column mean (unchanged) ----------------
__global__ void colmean_kernel(int src_sel, int n, float inv_n) {
    const float* Y = src_sel ? g_qtmp : g_tmp;
    int c = blockIdx.x;
    float s = 0.f;
    for (int r = threadIdx.x; r < n; r += 128) s += Y[(size_t)r * DSD + c];
    __shared__ float red[4];
    int lane = threadIdx.x & 31, w = threadIdx.x >> 5;
#pragma unroll
    for (int o = 16; o; o >>= 1) s += __shfl_xor_sync(0xffffffffu, s, o);
    if (lane == 0) red[w] = s;
    __syncthreads();
    if (threadIdx.x == 0) g_mean[c] = (red[0] + red[1] + red[2] + red[3]) * inv_n;
}

// ---- combine: writes stride-DSP output with zero-padded tail (unchanged) ----
__global__ void combine_kernel(const float* __restrict__ base_tab, const int* __restrict__ bidx,
                               int y_sel, const float* __restrict__ w, int dst_sel, int n) {
    const float* Y = y_sel ? g_qtmp : g_tmp;
    float* out = (dst_sel == 0) ? g_src : (dst_sel == 1) ? g_tgt : g_q;
    int r = blockIdx.x;
    if (r >= n) return;
    int br = bidx ? get_id(bidx, r) : r;
    const float* b = base_tab + (size_t)br * DSD;
    const float* y = Y + (size_t)r * DSD;
    float sb = 0.f, sc = 0.f;
    for (int i = threadIdx.x; i < DSD; i += 128) {
        float vb = b[i];
        sb += vb * vb;
        float vc = y[i] - g_mean[i];
        sc += vc * vc;
    }
    int lane = threadIdx.x & 31, wrp = threadIdx.x >> 5;
#pragma unroll
    for (int o = 16; o; o >>= 1) {
        sb += __shfl_xor_sync(0xffffffffu, sb, o);
        sc += __shfl_xor_sync(0xffffffffu, sc, o);
    }
    __shared__ float rb[4], rc[4];
    __shared__ float ivb_s, ivc_s;
    if (lane == 0) { rb[wrp] = sb; rc[wrp] = sc; }
    __syncthreads();
    if (threadIdx.x == 0) {
        ivb_s = 1.0f / sqrtf(rb[0] + rb[1] + rb[2] + rb[3]);
        ivc_s = 1.0f / sqrtf(rc[0] + rc[1] + rc[2] + rc[3]);
    }
    __syncthreads();
    float ib = ivb_s, ic = ivc_s;
    for (int i = threadIdx.x; i < DSP; i += 128) {
        float v = 0.f;
        if (i < DSD) v = b[i] * ib + w[i] * (y[i] - g_mean[i]) * ic;
        out[(size_t)r * DSP + i] = v;
    }
}

// ---------------- bwd v2 (R11-verbatim, empirically fastest): 64x128 tile, 128 thr,
// 8x8 FFMA2, double-buffered, 51.2KB smem -> 4 blocks/SM. g_bwd bit-identical. ----------------
#define BWD_SMEM 51200
__global__ void __launch_bounds__(128, 1) bwd_kernel() {
    extern __shared__ __align__(16) float smb[];
    float* AsB[2] = {smb, smb + 32 * 68};
    float* BsB[2] = {smb + 64 * 68, smb + 64 * 68 + 32 * 132};
    float* scores = smb;  // 64*132 = 8448 floats (fits in 12800)
    float* cand = smb;    // 64*20 floats

    const int tid = threadIdx.x;
    const int r0 = blockIdx.x * 64;
    const int m0 = (tid >> 4) << 3;  // 8 row-groups
    const int n0 = (tid & 15) << 3;  // 16 col-threads
    const int srow = tid & 63;
    const int part = tid >> 6;

    float top[TOPK];
#pragma unroll
    for (int i = 0; i < TOPK; i++) top[i] = -3.0e38f;

    float4 pa[4], pb[8];

    for (int s0 = 0; s0 < VSZ; s0 += 128) {
        u64 acc[8][4];
#pragma unroll
        for (int i = 0; i < 8; i++)
#pragma unroll
            for (int jp = 0; jp < 4; jp++) acc[i][jp] = 0ull;

        // prefetch chunk 0 (k base 0)
#pragma unroll
        for (int cc = 0; cc < 4; cc++) {
            int j = cc * 128 + tid, m = j >> 3, kq = j & 7;
            int gr = r0 + m;
            pa[cc] = (gr < VTZ) ? *(const float4*)&g_tgt[(size_t)gr * DSP + kq * 4]
                                : make_float4(0.f, 0.f, 0.f, 0.f);
        }
#pragma unroll
        for (int cc = 0; cc < 8; cc++) {
            int j = cc * 128 + tid, n = j >> 3, kq = j & 7;
            int gs = s0 + n;
            pb[cc] = (gs < VSZ) ? *(const float4*)&g_src[(size_t)gs * DSP + kq * 4]
                                : make_float4(0.f, 0.f, 0.f, 0.f);
        }
        __syncthreads();  // previous s0's scan reads complete before smem overwrite
        {
            float* A = AsB[0];
            float* B = BsB[0];
#pragma unroll
            for (int cc = 0; cc < 4; cc++) {
                int j = cc * 128 + tid, m = j >> 3, kq = j & 7;
                A[(kq * 4 + 0) * 68 + m] = pa[cc].x;
                A[(kq * 4 + 1) * 68 + m] = pa[cc].y;
                A[(kq * 4 + 2) * 68 + m] = pa[cc].z;
                A[(kq * 4 + 3) * 68 + m] = pa[cc].w;
            }
#pragma unroll
            for (int cc = 0; cc < 8; cc++) {
                int j = cc * 128 + tid, n = j >> 3, kq = j & 7;
                B[(kq * 4 + 0) * 132 + n] = pb[cc].x;
                B[(kq * 4 + 1) * 132 + n] = pb[cc].y;
                B[(kq * 4 + 2) * 132 + n] = pb[cc].z;
                B[(kq * 4 + 3) * 132 + n] = pb[cc].w;
            }
        }
        __syncthreads();

        for (int c = 0; c < 10; c++) {
            if (c < 9) {
                const int kb = (c + 1) * 32;
#pragma unroll
                for (int cc = 0; cc < 4; cc++) {
                    int j = cc * 128 + tid, m = j >> 3, kq = j & 7;
                    int gr = r0 + m;
                    pa[cc] = (gr < VTZ) ? *(const float4*)&g_tgt[(size_t)gr * DSP + kb + kq * 4]
                                        : make_float4(0.f, 0.f, 0.f, 0.f);
                }
#pragma unroll
                for (int cc = 0; cc < 8; cc++) {
                    int j = cc * 128 + tid, n = j >> 3, kq = j & 7;
                    int gs = s0 + n;
                    pb[cc] = (gs < VSZ) ? *(const float4*)&g_src[(size_t)gs * DSP + kb + kq * 4]
                                        : make_float4(0.f, 0.f, 0.f, 0.f);
                }
            }
            const float* A = AsB[c & 1];
            const float* B = BsB[c & 1];
#pragma unroll 4
            for (int k = 0; k < 32; k++) {
                float4 a0 = *(const float4*)&A[k * 68 + m0];
                float4 a1 = *(const float4*)&A[k * 68 + m0 + 4];
                float4 b0 = *(const float4*)&B[k * 132 + n0];
                float4 b1 = *(const float4*)&B[k * 132 + n0 + 4];
                u64 bp0 = pack2(b0.x, b0.y), bp1 = pack2(b0.z, b0.w);
                u64 bp2 = pack2(b1.x, b1.y), bp3 = pack2(b1.z, b1.w);
                float am[8] = {a0.x, a0.y, a0.z, a0.w, a1.x, a1.y, a1.z, a1.w};
#pragma unroll
                for (int i = 0; i < 8; i++) {
                    u64 a2 = pack2(am[i], am[i]);
                    fma2(acc[i][0], a2, bp0);
                    fma2(acc[i][1], a2, bp1);
                    fma2(acc[i][2], a2, bp2);
                    fma2(acc[i][3], a2, bp3);
                }
            }
            __syncthreads();
            if (c < 9) {
                float* An = AsB[(c + 1) & 1];
                float* Bn = BsB[(c + 1) & 1];
#pragma unroll
                for (int cc = 0; cc < 4; cc++) {
                    int j = cc * 128 + tid, m = j >> 3, kq = j & 7;
                    An[(kq * 4 + 0) * 68 + m] = pa[cc].x;
                    An[(kq * 4 + 1) * 68 + m] = pa[cc].y;
                    An[(kq * 4 + 2) * 68 + m] = pa[cc].z;
                    An[(kq * 4 + 3) * 68 + m] = pa[cc].w;
                }
#pragma unroll
                for (int cc = 0; cc < 8; cc++) {
                    int j = cc * 128 + tid, n = j >> 3, kq = j & 7;
                    Bn[(kq * 4 + 0) * 132 + n] = pb[cc].x;
                    Bn[(kq * 4 + 1) * 132 + n] = pb[cc].y;
                    Bn[(kq * 4 + 2) * 132 + n] = pb[cc].z;
                    Bn[(kq * 4 + 3) * 132 + n] = pb[cc].w;
                }
                __syncthreads();
            }
        }
        // stage scores (overwrites buffers; all compute synced above)
#pragma unroll
        for (int i = 0; i < 8; i++)
#pragma unroll
            for (int jp = 0; jp < 4; jp++) {
                float2 v = unpack2(acc[i][jp]);
                *(float2*)&scores[(m0 + i) * 132 + n0 + jp * 2] = v;
            }
        __syncthreads();
        // per-thread partial top-10 over 64 columns
#pragma unroll 8
        for (int cc = 0; cc < 64; cc++) {
            int n = part * 64 + cc;
            int gs = s0 + n;
            float v = scores[srow * 132 + n];
            if (gs < VSZ && v > top[TOPK - 1]) {
#pragma unroll
                for (int i = 0; i < TOPK; i++) {
                    if (v > top[i]) { float t = top[i]; top[i] = v; v = t; }
                }
            }
        }
        // no sync here: next s0's first __syncthreads covers the scan reads
    }
    __syncthreads();
#pragma unroll
    for (int i = 0; i < TOPK; i++) cand[srow * 20 + part * 10 + i] = top[i];
    __syncthreads();
    if (tid < 64 && r0 + tid < VTZ) {
        float* c = cand + tid * 20;
        float sum = 0.f;
        for (int j = 0; j < TOPK; j++) {
            float mx = -3.0e38f;
            int mi = 0;
            for (int i = 0; i < 20; i++) {
                float v = c[i];
                if (v > mx) { mx = v; mi = i; }
            }
            sum += mx;
            c[mi] = -3.0e38f;
        }
        g_bwd[r0 + tid] = sum * (1.0f / TOPK);
    }
}

// ---------------- final: UNTOUCHED numerics (R9/R11/R12-passing) ----------------
__global__ void final_kernel(float* __restrict__ out) {
    __shared__ __align__(16) float Aq[DSD * 16];
    __shared__ __align__(16) float U[20 * 256];
    const int tid = threadIdx.x;
    const int b0 = blockIdx.x * 16;

    for (int i = tid; i < 16 * DSD; i += 256) {
        int m = i / DSD, k = i - m * DSD;
        Aq[k * 16 + m] = g_q[(size_t)(b0 + m) * DSP + k];
    }
    const int rowg = tid >> 6;
    const int colg = tid & 63;
    const int srow = tid >> 4;
    const int scol0 = (tid & 15) * 16;
    float tv[TOPK];
    int ti[TOPK];
#pragma unroll
    for (int i = 0; i < TOPK; i++) { tv[i] = -3.0e38f; ti[i] = 0x7fffffff; }
    __syncthreads();

    for (int t0 = 0; t0 < VTZ; t0 += 256) {
        float sum[4][4], comp[4][4];
#pragma unroll
        for (int i = 0; i < 4; i++)
#pragma unroll
            for (int j = 0; j < 4; j++) { sum[i][j] = 0.f; comp[i][j] = 0.f; }

        for (int k0 = 0; k0 < DSD; k0 += 20) {
            for (int i = tid; i < 256 * 20; i += 256) {
                int n = i / 20, k = i - n * 20;
                int gt = t0 + n;
                U[k * 256 + n] = (gt < VTZ) ? g_tgt[(size_t)gt * DSP + k0 + k] : 0.f;
            }
            __syncthreads();
            float a0[4][4], a1[4][4];
#pragma unroll
            for (int i = 0; i < 4; i++)
#pragma unroll
                for (int j = 0; j < 4; j++) { a0[i][j] = 0.f; a1[i][j] = 0.f; }
#pragma unroll 5
            for (int k = 0; k < 20; k += 2) {
                float4 xa = *(const float4*)&Aq[(k0 + k) * 16 + rowg * 4];
                float4 xb = *(const float4*)&U[k * 256 + colg * 4];
                float4 ya = *(const float4*)&Aq[(k0 + k + 1) * 16 + rowg * 4];
                float4 yb = *(const float4*)&U[(k + 1) * 256 + colg * 4];
                float av0[4] = {xa.x, xa.y, xa.z, xa.w};
                float bv0[4] = {xb.x, xb.y, xb.z, xb.w};
                float av1[4] = {ya.x, ya.y, ya.z, ya.w};
                float bv1[4] = {yb.x, yb.y, yb.z, yb.w};
#pragma unroll
                for (int i = 0; i < 4; i++)
#pragma unroll
                    for (int j = 0; j < 4; j++) {
                        a0[i][j] = fmaf(av0[i], bv0[j], a0[i][j]);
                        a1[i][j] = fmaf(av1[i], bv1[j], a1[i][j]);
                    }
            }
#pragma unroll
            for (int i = 0; i < 4; i++)
#pragma unroll
                for (int j = 0; j < 4; j++) {
                    float x = a0[i][j] + a1[i][j];
                    float t = sum[i][j] + x;
                    float e = (sum[i][j] - t) + x;
                    comp[i][j] += e;
                    sum[i][j] = t;
                }
            __syncthreads();
        }
#pragma unroll
        for (int j = 0; j < 4; j++) {
            int gt = t0 + colg * 4 + j;
            float bw = (gt < VTZ) ? g_bwd[gt] : 0.f;
#pragma unroll
            for (int i = 0; i < 4; i++) {
                float sim = sum[i][j] + comp[i][j];
                U[(rowg * 4 + i) * 260 + colg * 4 + j] = 2.f * sim - bw;
            }
        }
        __syncthreads();
#pragma unroll
        for (int c = 0; c < 16; c++) {
            int gt = t0 + scol0 + c;
            if (gt < VTZ) {
                float v = U[srow * 260 + scol0 + c];
                if (v > tv[TOPK - 1]) {
                    int id = gt;
#pragma unroll
                    for (int i = 0; i < TOPK; i++) {
                        if (v > tv[i]) {
                            float t = tv[i]; tv[i] = v; v = t;
                            int tt = ti[i]; ti[i] = id; id = tt;
                        }
                    }
                }
            }
        }
        __syncthreads();
    }
    float* cv = U;
    int* ci = (int*)(U + 16 * 160);
    const int part = tid & 15;
#pragma unroll
    for (int i = 0; i < TOPK; i++) {
        cv[srow * 160 + part * 10 + i] = tv[i];
        ci[srow * 160 + part * 10 + i] = ti[i];
    }
    __syncthreads();
    if (tid < 16) {
        float* v = cv + tid * 160;
        int* id = ci + tid * 160;
        int b = b0 + tid;
        for (int j = 0; j < TOPK; j++) {
            float mx = -3.0e38f;
            int mi = -1, midx = 0x7fffffff;
            for (int i = 0; i < 160; i++) {
                float vv = v[i];
                int vi = id[i];
                if (vv > mx || (vv == mx && vi < midx)) { mx = vv; mi = i; midx = vi; }
            }
            out[b * TOPK + j] = (float)midx;
            v[mi] = -3.0e38f;
        }
    }
}

// ---------------- launch ----------------
extern "C" void kernel_launch(void* const* d_in, const int* in_sizes, int n_in,
                              void* d_out, int out_size) {
    const int* sid;
    const int* cid;
    const float *sst, *stt, *cst, *ctt, *W1, *b1, *W2, *b2, *W3, *b3, *W4, *b4, *w1, *w2;

    long s0 = (n_in >= 16) ? (long)in_sizes[0] : 0;
    bool alphabetical = (s0 == 307200L) || (s0 == 307200L * 4L);

    if (alphabetical) {
        W1 = (const float*)d_in[0];  W2 = (const float*)d_in[1];
        W3 = (const float*)d_in[2];  W4 = (const float*)d_in[3];
        b1 = (const float*)d_in[4];  b2 = (const float*)d_in[5];
        b3 = (const float*)d_in[6];  b4 = (const float*)d_in[7];
        cid = (const int*)d_in[8];
        cst = (const float*)d_in[9];
        ctt = (const float*)d_in[10];
        sid = (const int*)d_in[11];
        sst = (const float*)d_in[12];
        stt = (const float*)d_in[13];
        w1 = (const float*)d_in[14]; w2 = (const float*)d_in[15];
    } else {
        sid = (const int*)d_in[0];
        cid = (const int*)d_in[1];
        sst = (const float*)d_in[2];
        stt = (const float*)d_in[3];
        cst = (const float*)d_in[4];
        ctt = (const float*)d_in[5];
        W1 = (const float*)d_in[6];  b1 = (const float*)d_in[7];
        W2 = (const float*)d_in[8];  b2 = (const float*)d_in[9];
        W3 = (const float*)d_in[10]; b3 = (const float*)d_in[11];
        W4 = (const float*)d_in[12]; b4 = (const float*)d_in[13];
        w1 = (const float*)d_in[14]; w2 = (const float*)d_in[15];
    }
    float* out = (float*)d_out;

    cudaFuncSetAttribute(bwd_kernel, cudaFuncAttributeMaxDynamicSharedMemorySize, BWD_SMEM);
    cudaFuncSetAttribute(gemm_tanh2_kernel, cudaFuncAttributeMaxDynamicSharedMemorySize, GEMM_SMEM);

    // canary FIRST
    fallback_fill_kernel<<<(BQN * TOPK + 255) / 256, 256>>>(out, BQN * TOPK);

    dim3 gg2((DSD + 127) / 128, (VSZ + 63) / 64);  // (3, 313)

    // source-context MLP
    gemm_tanh2_kernel<<<gg2, 128, GEMM_SMEM>>>(cst, 0, W1, b1, 0, VSZ, DSD, DCD, DCD);
    gemm_tanh2_kernel<<<gg2, 128, GEMM_SMEM>>>(nullptr, 1, W3, b3, 1, VSZ, DSD, DSD, DSD);
    l2rows_kernel<<<VSZ, 128>>>(nullptr, 0, VSZ);
    colmean_kernel<<<DSD, 128>>>(0, VSZ, 1.0f / VSZ);
    combine_kernel<<<VSZ, 128>>>(sst, nullptr, 0, w1, 0, VSZ);

    // query path
    l2rows_kernel<<<BQN, 128>>>(cid, 1, BQN);
    colmean_kernel<<<DSD, 128>>>(1, BQN, 1.0f / BQN);
    combine_kernel<<<BQN, 128>>>(sst, sid, 1, w1, 2, BQN);

    // target-context MLP
    gemm_tanh2_kernel<<<gg2, 128, GEMM_SMEM>>>(ctt, 0, W2, b2, 0, VTZ, DSD, DCD, DCD);
    gemm_tanh2_kernel<<<gg2, 128, GEMM_SMEM>>>(nullptr, 1, W4, b4, 1, VTZ, DSD, DSD, DSD);
    l2rows_kernel<<<VTZ, 128>>>(nullptr, 0, VTZ);
    colmean_kernel<<<DSD, 128>>>(0, VTZ, 1.0f / VTZ);
    combine_kernel<<<VTZ, 128>>>(stt, nullptr, 0, w2, 1, VTZ);

    // backward CSLS term (v2: R11-verbatim, empirically fastest)
    bwd_kernel<<<(VTZ + 63) / 64, 128, BWD_SMEM>>>();

    // final scores + top-k indices
    final_kernel<<<BQN / 16, 256>>>(out);
}

// round 16
// speedup vs baseline: 1.2217x; 1.1150x over previous
#include <cuda_runtime.h>
#include <math.h>

#define VSZ 20000
#define VTZ 20000
#define BQN 2000
#define DSD 300
#define DSP 320   // padded k-stride for src/tgt/q combined vectors (zero tail)
#define DCD 1024
#define TOPK 10

typedef unsigned long long u64;

// ---------------- scratch: static device globals ----------------
__device__ float g_h[(size_t)VSZ * DSD];
__device__ float g_pre[(size_t)VSZ * DSD];
__device__ float g_tmp[(size_t)VSZ * DSD];
__device__ float g_src[(size_t)VSZ * DSP];   // src_comb, stride 320, zero-padded
__device__ float g_tgt[(size_t)VTZ * DSP];   // tgt_comb, stride 320, zero-padded
__device__ float g_q[(size_t)BQN * DSP];     // queries,  stride 320, zero-padded
__device__ float g_qtmp[(size_t)BQN * DSD];
__device__ float g_mean[DSD];
__device__ float g_bwd[VTZ];

// ---------------- packed fp32x2 helpers (bit-identical IEEE fp32 per half) ----------------
__device__ __forceinline__ u64 pack2(float x, float y) {
    u64 r; asm("mov.b64 %0, {%1, %2};" : "=l"(r) : "f"(x), "f"(y)); return r;
}
__device__ __forceinline__ void fma2(u64& acc, u64 a, u64 b) {
    asm("fma.rn.f32x2 %0, %1, %2, %0;" : "+l"(acc) : "l"(a), "l"(b));
}
__device__ __forceinline__ float2 unpack2(u64 v) {
    float2 r; asm("mov.b64 {%0, %1}, %2;" : "=f"(r.x), "=f"(r.y) : "l"(v)); return r;
}

// ---------------- canary fallback ----------------
__global__ void fallback_fill_kernel(float* __restrict__ out, int n) {
    int i = blockIdx.x * 256 + threadIdx.x;
    if (i < n) out[i] = -30000.0f;
}

__device__ __forceinline__ int get_id(const int* __restrict__ idx, int r) {
    bool is64 = (idx[1] == 0) && (idx[3] == 0) && (idx[5] == 0) && (idx[7] == 0);
    int v = is64 ? idx[2 * r] : idx[r];
    return min(max(v, 0), VSZ - 1);
}

// ---------------- GEMM v3: like R12 v2 but conflict-free B reads (n_lo / 64+n_lo split) ----
#define GEMM_SMEM 51200
__global__ void __launch_bounds__(128) gemm_tanh2_kernel(
    const float* __restrict__ Ain, int a_sel,
    const float* __restrict__ W, const float* __restrict__ bias,
    int c_sel, int M, int N, int K, int lda) {
    const float* A = (a_sel == 0) ? Ain : (const float*)g_h;
    float* C = (c_sel == 0) ? g_h : g_pre;
    extern __shared__ __align__(16) float sm[];
    float* AsB[2] = {sm, sm + 32 * 68};
    float* BsB[2] = {sm + 2 * 32 * 68, sm + 2 * 32 * 68 + 32 * 132};

    const int tid = threadIdx.x;
    const int row0 = blockIdx.y * 64, col0 = blockIdx.x * 128;
    const int m0 = (tid >> 4) << 3;
    const int n_lo = (tid & 15) << 2;   // consecutive float4 group -> conflict-free 2-phase
    const int nch = (K + 31) / 32;

    u64 acc[8][4];
#pragma unroll
    for (int i = 0; i < 8; i++)
#pragma unroll
        for (int jp = 0; jp < 4; jp++) acc[i][jp] = 0ull;

    float4 pa[4], pb[8];
#pragma unroll
    for (int cc = 0; cc < 4; cc++) {
        int j = cc * 128 + tid, m = j >> 3, kq = j & 7;
        int gr = row0 + m, gk = kq * 4;
        pa[cc] = (gr < M && gk < K) ? *(const float4*)&A[(size_t)gr * lda + gk]
                                    : make_float4(0.f, 0.f, 0.f, 0.f);
    }
#pragma unroll
    for (int cc = 0; cc < 8; cc++) {
        int j = cc * 128 + tid, n = j >> 3, kq = j & 7;
        int gc = col0 + n, gk = kq * 4;
        pb[cc] = (gc < N && gk < K) ? *(const float4*)&W[(size_t)gc * K + gk]
                                    : make_float4(0.f, 0.f, 0.f, 0.f);
    }
    {
        float* Ax = AsB[0];
        float* Bx = BsB[0];
#pragma unroll
        for (int cc = 0; cc < 4; cc++) {
            int j = cc * 128 + tid, m = j >> 3, kq = j & 7;
            Ax[(kq * 4 + 0) * 68 + m] = pa[cc].x;
            Ax[(kq * 4 + 1) * 68 + m] = pa[cc].y;
            Ax[(kq * 4 + 2) * 68 + m] = pa[cc].z;
            Ax[(kq * 4 + 3) * 68 + m] = pa[cc].w;
        }
#pragma unroll
        for (int cc = 0; cc < 8; cc++) {
            int j = cc * 128 + tid, n = j >> 3, kq = j & 7;
            Bx[(kq * 4 + 0) * 132 + n] = pb[cc].x;
            Bx[(kq * 4 + 1) * 132 + n] = pb[cc].y;
            Bx[(kq * 4 + 2) * 132 + n] = pb[cc].z;
            Bx[(kq * 4 + 3) * 132 + n] = pb[cc].w;
        }
    }
    __syncthreads();

    for (int c = 0; c < nch; c++) {
        if (c + 1 < nch) {
            const int kb = (c + 1) * 32;
#pragma unroll
            for (int cc = 0; cc < 4; cc++) {
                int j = cc * 128 + tid, m = j >> 3, kq = j & 7;
                int gr = row0 + m, gk = kb + kq * 4;
                pa[cc] = (gr < M && gk < K) ? *(const float4*)&A[(size_t)gr * lda + gk]
                                            : make_float4(0.f, 0.f, 0.f, 0.f);
            }
#pragma unroll
            for (int cc = 0; cc < 8; cc++) {
                int j = cc * 128 + tid, n = j >> 3, kq = j & 7;
                int gc = col0 + n, gk = kb + kq * 4;
                pb[cc] = (gc < N && gk < K) ? *(const float4*)&W[(size_t)gc * K + gk]
                                            : make_float4(0.f, 0.f, 0.f, 0.f);
            }
        }
        const float* Ab = AsB[c & 1];
        const float* Bb = BsB[c & 1];
#pragma unroll 4
        for (int k = 0; k < 32; k++) {
            float4 a0 = *(const float4*)&Ab[k * 68 + m0];
            float4 a1 = *(const float4*)&Ab[k * 68 + m0 + 4];
            float4 b0 = *(const float4*)&Bb[k * 132 + n_lo];        // cols n_lo..n_lo+3
            float4 b1 = *(const float4*)&Bb[k * 132 + 64 + n_lo];   // cols 64+n_lo..+3
            u64 bp0 = pack2(b0.x, b0.y), bp1 = pack2(b0.z, b0.w);
            u64 bp2 = pack2(b1.x, b1.y), bp3 = pack2(b1.z, b1.w);
            float am[8] = {a0.x, a0.y, a0.z, a0.w, a1.x, a1.y, a1.z, a1.w};
#pragma unroll
            for (int i = 0; i < 8; i++) {
                u64 a2 = pack2(am[i], am[i]);
                fma2(acc[i][0], a2, bp0);
                fma2(acc[i][1], a2, bp1);
                fma2(acc[i][2], a2, bp2);
                fma2(acc[i][3], a2, bp3);
            }
        }
        __syncthreads();
        if (c + 1 < nch) {
            float* An = AsB[(c + 1) & 1];
            float* Bn = BsB[(c + 1) & 1];
#pragma unroll
            for (int cc = 0; cc < 4; cc++) {
                int j = cc * 128 + tid, m = j >> 3, kq = j & 7;
                An[(kq * 4 + 0) * 68 + m] = pa[cc].x;
                An[(kq * 4 + 1) * 68 + m] = pa[cc].y;
                An[(kq * 4 + 2) * 68 + m] = pa[cc].z;
                An[(kq * 4 + 3) * 68 + m] = pa[cc].w;
            }
#pragma unroll
            for (int cc = 0; cc < 8; cc++) {
                int j = cc * 128 + tid, n = j >> 3, kq = j & 7;
                Bn[(kq * 4 + 0) * 132 + n] = pb[cc].x;
                Bn[(kq * 4 + 1) * 132 + n] = pb[cc].y;
                Bn[(kq * 4 + 2) * 132 + n] = pb[cc].z;
                Bn[(kq * 4 + 3) * 132 + n] = pb[cc].w;
            }
            __syncthreads();
        }
    }
    // epilogue: tanh(acc + bias); columns per jp: 0,1 -> n_lo block; 2,3 -> 64+n_lo block
#pragma unroll
    for (int i = 0; i < 8; i++) {
        int gr = row0 + m0 + i;
        if (gr >= M) continue;
#pragma unroll
        for (int jp = 0; jp < 4; jp++) {
            float2 v = unpack2(acc[i][jp]);
            int gc = (jp < 2) ? (col0 + n_lo + jp * 2) : (col0 + 64 + n_lo + (jp - 2) * 2);
            if (gc < N) C[(size_t)gr * N + gc] = tanhf(v.x + bias[gc]);
            if (gc + 1 < N) C[(size_t)gr * N + gc + 1] = tanhf(v.y + bias[gc + 1]);
        }
    }
}

// ---------------- row L2 normalize (unchanged) ----------------
__global__ void l2rows_kernel(const int* __restrict__ idx, int dst_sel, int n) {
    float* out = dst_sel ? g_qtmp : g_tmp;
    int r = blockIdx.x;
    if (r >= n) return;
    int sr = idx ? get_id(idx, r) : r;
    const float* src = g_pre + (size_t)sr * DSD;
    float s = 0.f;
    for (int i = threadIdx.x; i < DSD; i += 128) {
        float x = src[i];
        s += x * x;
    }
    __shared__ float red[4];
    __shared__ float s_inv;
    int lane = threadIdx.x & 31, w = threadIdx.x >> 5;
#pragma unroll
    for (int o = 16; o; o >>= 1) s += __shfl_xor_sync(0xffffffffu, s, o);
    if (lane == 0) red[w] = s;
    __syncthreads();
    if (threadIdx.x == 0) s_inv = 1.0f / sqrtf(red[0] + red[1] + red[2] + red[3]);
    __syncthreads();
    float inv = s_inv;
    for (int i = threadIdx.x; i < DSD; i += 128) out[(size_t)r * DSD + i] = src[i] * inv;
}

// ---------------- column mean (unchanged) ----------------
__global__ void colmean_kernel(int src_sel, int n, float inv_n) {
    const float* Y = src_sel ? g_qtmp : g_tmp;
    int c = blockIdx.x;
    float s = 0.f;
    for (int r = threadIdx.x; r < n; r += 128) s += Y[(size_t)r * DSD + c];
    __shared__ float red[4];
    int lane = threadIdx.x & 31, w = threadIdx.x >> 5;
#pragma unroll
    for (int o = 16; o; o >>= 1) s += __shfl_xor_sync(0xffffffffu, s, o);
    if (lane == 0) red[w] = s;
    __syncthreads();
    if (threadIdx.x == 0) g_mean[c] = (red[0] + red[1] + red[2] + red[3]) * inv_n;
}

// ---- combine: writes stride-DSP output with zero-padded tail (unchanged) ----
__global__ void combine_kernel(const float* __restrict__ base_tab, const int* __restrict__ bidx,
                               int y_sel, const float* __restrict__ w, int dst_sel, int n) {
    const float* Y = y_sel ? g_qtmp : g_tmp;
    float* out = (dst_sel == 0) ? g_src : (dst_sel == 1) ? g_tgt : g_q;
    int r = blockIdx.x;
    if (r >= n) return;
    int br = bidx ? get_id(bidx, r) : r;
    const float* b = base_tab + (size_t)br * DSD;
    const float* y = Y + (size_t)r * DSD;
    float sb = 0.f, sc = 0.f;
    for (int i = threadIdx.x; i < DSD; i += 128) {
        float vb = b[i];
        sb += vb * vb;
        float vc = y[i] - g_mean[i];
        sc += vc * vc;
    }
    int lane = threadIdx.x & 31, wrp = threadIdx.x >> 5;
#pragma unroll
    for (int o = 16; o; o >>= 1) {
        sb += __shfl_xor_sync(0xffffffffu, sb, o);
        sc += __shfl_xor_sync(0xffffffffu, sc, o);
    }
    __shared__ float rb[4], rc[4];
    __shared__ float ivb_s, ivc_s;
    if (lane == 0) { rb[wrp] = sb; rc[wrp] = sc; }
    __syncthreads();
    if (threadIdx.x == 0) {
        ivb_s = 1.0f / sqrtf(rb[0] + rb[1] + rb[2] + rb[3]);
        ivc_s = 1.0f / sqrtf(rc[0] + rc[1] + rc[2] + rc[3]);
    }
    __syncthreads();
    float ib = ivb_s, ic = ivc_s;
    for (int i = threadIdx.x; i < DSP; i += 128) {
        float v = 0.f;
        if (i < DSD) v = b[i] * ib + w[i] * (y[i] - g_mean[i]) * ic;
        out[(size_t)r * DSP + i] = v;
    }
}

// ---------------- bwd v5: v2 layout + conflict-free B reads (n_lo / 64+n_lo split) ----------------
// Same per-output sequential k-chain => g_bwd bit-identical. 51.2KB smem.
#define BWD_SMEM 51200
__global__ void __launch_bounds__(128, 1) bwd_kernel() {
    extern __shared__ __align__(16) float smb[];
    float* AsB[2] = {smb, smb + 32 * 68};
    float* BsB[2] = {smb + 64 * 68, smb + 64 * 68 + 32 * 132};
    float* scores = smb;  // 64*132 = 8448 floats
    float* cand = smb;    // 64*20 floats

    const int tid = threadIdx.x;
    const int r0 = blockIdx.x * 64;
    const int m0 = (tid >> 4) << 3;   // 8 row-groups
    const int n_lo = (tid & 15) << 2; // consecutive float4 group -> conflict-free
    const int srow = tid & 63;
    const int part = tid >> 6;

    float top[TOPK];
#pragma unroll
    for (int i = 0; i < TOPK; i++) top[i] = -3.0e38f;

    float4 pa[4], pb[8];

    for (int s0 = 0; s0 < VSZ; s0 += 128) {
        u64 acc[8][4];
#pragma unroll
        for (int i = 0; i < 8; i++)
#pragma unroll
            for (int jp = 0; jp < 4; jp++) acc[i][jp] = 0ull;

        // prefetch chunk 0 (k base 0)
#pragma unroll
        for (int cc = 0; cc < 4; cc++) {
            int j = cc * 128 + tid, m = j >> 3, kq = j & 7;
            int gr = r0 + m;
            pa[cc] = (gr < VTZ) ? *(const float4*)&g_tgt[(size_t)gr * DSP + kq * 4]
                                : make_float4(0.f, 0.f, 0.f, 0.f);
        }
#pragma unroll
        for (int cc = 0; cc < 8; cc++) {
            int j = cc * 128 + tid, n = j >> 3, kq = j & 7;
            int gs = s0 + n;
            pb[cc] = (gs < VSZ) ? *(const float4*)&g_src[(size_t)gs * DSP + kq * 4]
                                : make_float4(0.f, 0.f, 0.f, 0.f);
        }
        __syncthreads();  // previous s0's scan reads complete before smem overwrite
        {
            float* A = AsB[0];
            float* B = BsB[0];
#pragma unroll
            for (int cc = 0; cc < 4; cc++) {
                int j = cc * 128 + tid, m = j >> 3, kq = j & 7;
                A[(kq * 4 + 0) * 68 + m] = pa[cc].x;
                A[(kq * 4 + 1) * 68 + m] = pa[cc].y;
                A[(kq * 4 + 2) * 68 + m] = pa[cc].z;
                A[(kq * 4 + 3) * 68 + m] = pa[cc].w;
            }
#pragma unroll
            for (int cc = 0; cc < 8; cc++) {
                int j = cc * 128 + tid, n = j >> 3, kq = j & 7;
                B[(kq * 4 + 0) * 132 + n] = pb[cc].x;
                B[(kq * 4 + 1) * 132 + n] = pb[cc].y;
                B[(kq * 4 + 2) * 132 + n] = pb[cc].z;
                B[(kq * 4 + 3) * 132 + n] = pb[cc].w;
            }
        }
        __syncthreads();

        for (int c = 0; c < 10; c++) {
            if (c < 9) {
                const int kb = (c + 1) * 32;
#pragma unroll
                for (int cc = 0; cc < 4; cc++) {
                    int j = cc * 128 + tid, m = j >> 3, kq = j & 7;
                    int gr = r0 + m;
                    pa[cc] = (gr < VTZ) ? *(const float4*)&g_tgt[(size_t)gr * DSP + kb + kq * 4]
                                        : make_float4(0.f, 0.f, 0.f, 0.f);
                }
#pragma unroll
                for (int cc = 0; cc < 8; cc++) {
                    int j = cc * 128 + tid, n = j >> 3, kq = j & 7;
                    int gs = s0 + n;
                    pb[cc] = (gs < VSZ) ? *(const float4*)&g_src[(size_t)gs * DSP + kb + kq * 4]
                                        : make_float4(0.f, 0.f, 0.f, 0.f);
                }
            }
            const float* A = AsB[c & 1];
            const float* B = BsB[c & 1];
#pragma unroll 4
            for (int k = 0; k < 32; k++) {
                float4 a0 = *(const float4*)&A[k * 68 + m0];
                float4 a1 = *(const float4*)&A[k * 68 + m0 + 4];
                float4 b0 = *(const float4*)&B[k * 132 + n_lo];        // cols n_lo..+3
                float4 b1 = *(const float4*)&B[k * 132 + 64 + n_lo];   // cols 64+n_lo..+3
                u64 bp0 = pack2(b0.x, b0.y), bp1 = pack2(b0.z, b0.w);
                u64 bp2 = pack2(b1.x, b1.y), bp3 = pack2(b1.z, b1.w);
                float am[8] = {a0.x, a0.y, a0.z, a0.w, a1.x, a1.y, a1.z, a1.w};
#pragma unroll
                for (int i = 0; i < 8; i++) {
                    u64 a2 = pack2(am[i], am[i]);
                    fma2(acc[i][0], a2, bp0);
                    fma2(acc[i][1], a2, bp1);
                    fma2(acc[i][2], a2, bp2);
                    fma2(acc[i][3], a2, bp3);
                }
            }
            __syncthreads();
            if (c < 9) {
                float* An = AsB[(c + 1) & 1];
                float* Bn = BsB[(c + 1) & 1];
#pragma unroll
                for (int cc = 0; cc < 4; cc++) {
                    int j = cc * 128 + tid, m = j >> 3, kq = j & 7;
                    An[(kq * 4 + 0) * 68 + m] = pa[cc].x;
                    An[(kq * 4 + 1) * 68 + m] = pa[cc].y;
                    An[(kq * 4 + 2) * 68 + m] = pa[cc].z;
                    An[(kq * 4 + 3) * 68 + m] = pa[cc].w;
                }
#pragma unroll
                for (int cc = 0; cc < 8; cc++) {
                    int j = cc * 128 + tid, n = j >> 3, kq = j & 7;
                    Bn[(kq * 4 + 0) * 132 + n] = pb[cc].x;
                    Bn[(kq * 4 + 1) * 132 + n] = pb[cc].y;
                    Bn[(kq * 4 + 2) * 132 + n] = pb[cc].z;
                    Bn[(kq * 4 + 3) * 132 + n] = pb[cc].w;
                }
                __syncthreads();
            }
        }
        // stage scores: jp0,1 -> cols n_lo..; jp2,3 -> cols 64+n_lo..
#pragma unroll
        for (int i = 0; i < 8; i++) {
            float2 v0 = unpack2(acc[i][0]);
            float2 v1 = unpack2(acc[i][1]);
            float2 v2 = unpack2(acc[i][2]);
            float2 v3 = unpack2(acc[i][3]);
            *(float2*)&scores[(m0 + i) * 132 + n_lo] = v0;
            *(float2*)&scores[(m0 + i) * 132 + n_lo + 2] = v1;
            *(float2*)&scores[(m0 + i) * 132 + 64 + n_lo] = v2;
            *(float2*)&scores[(m0 + i) * 132 + 64 + n_lo + 2] = v3;
        }
        __syncthreads();
        // per-thread partial top-10 over 64 columns
#pragma unroll 8
        for (int cc = 0; cc < 64; cc++) {
            int n = part * 64 + cc;
            int gs = s0 + n;
            float v = scores[srow * 132 + n];
            if (gs < VSZ && v > top[TOPK - 1]) {
#pragma unroll
                for (int i = 0; i < TOPK; i++) {
                    if (v > top[i]) { float t = top[i]; top[i] = v; v = t; }
                }
            }
        }
        // no sync here: next s0's first __syncthreads covers the scan reads
    }
    __syncthreads();
#pragma unroll
    for (int i = 0; i < TOPK; i++) cand[srow * 20 + part * 10 + i] = top[i];
    __syncthreads();
    if (tid < 64 && r0 + tid < VTZ) {
        float* c = cand + tid * 20;
        float sum = 0.f;
        for (int j = 0; j < TOPK; j++) {
            float mx = -3.0e38f;
            int mi = 0;
            for (int i = 0; i < 20; i++) {
                float v = c[i];
                if (v > mx) { mx = v; mi = i; }
            }
            sum += mx;
            c[mi] = -3.0e38f;
        }
        g_bwd[r0 + tid] = sum * (1.0f / TOPK);
    }
}

// ---------------- final: UNTOUCHED numerics (R9/R11/R12/R15-passing) ----------------
__global__ void final_kernel(float* __restrict__ out) {
    __shared__ __align__(16) float Aq[DSD * 16];
    __shared__ __align__(16) float U[20 * 256];
    const int tid = threadIdx.x;
    const int b0 = blockIdx.x * 16;

    for (int i = tid; i < 16 * DSD; i += 256) {
        int m = i / DSD, k = i - m * DSD;
        Aq[k * 16 + m] = g_q[(size_t)(b0 + m) * DSP + k];
    }
    const int rowg = tid >> 6;
    const int colg = tid & 63;
    const int srow = tid >> 4;
    const int scol0 = (tid & 15) * 16;
    float tv[TOPK];
    int ti[TOPK];
#pragma unroll
    for (int i = 0; i < TOPK; i++) { tv[i] = -3.0e38f; ti[i] = 0x7fffffff; }
    __syncthreads();

    for (int t0 = 0; t0 < VTZ; t0 += 256) {
        float sum[4][4], comp[4][4];
#pragma unroll
        for (int i = 0; i < 4; i++)
#pragma unroll
            for (int j = 0; j < 4; j++) { sum[i][j] = 0.f; comp[i][j] = 0.f; }

        for (int k0 = 0; k0 < DSD; k0 += 20) {
            for (int i = tid; i < 256 * 20; i += 256) {
                int n = i / 20, k = i - n * 20;
                int gt = t0 + n;
                U[k * 256 + n] = (gt < VTZ) ? g_tgt[(size_t)gt * DSP + k0 + k] : 0.f;
            }
            __syncthreads();
            float a0[4][4], a1[4][4];
#pragma unroll
            for (int i = 0; i < 4; i++)
#pragma unroll
                for (int j = 0; j < 4; j++) { a0[i][j] = 0.f; a1[i][j] = 0.f; }
#pragma unroll 5
            for (int k = 0; k < 20; k += 2) {
                float4 xa = *(const float4*)&Aq[(k0 + k) * 16 + rowg * 4];
                float4 xb = *(const float4*)&U[k * 256 + colg * 4];
                float4 ya = *(const float4*)&Aq[(k0 + k + 1) * 16 + rowg * 4];
                float4 yb = *(const float4*)&U[(k + 1) * 256 + colg * 4];
                float av0[4] = {xa.x, xa.y, xa.z, xa.w};
                float bv0[4] = {xb.x, xb.y, xb.z, xb.w};
                float av1[4] = {ya.x, ya.y, ya.z, ya.w};
                float bv1[4] = {yb.x, yb.y, yb.z, yb.w};
#pragma unroll
                for (int i = 0; i < 4; i++)
#pragma unroll
                    for (int j = 0; j < 4; j++) {
                        a0[i][j] = fmaf(av0[i], bv0[j], a0[i][j]);
                        a1[i][j] = fmaf(av1[i], bv1[j], a1[i][j]);
                    }
            }
#pragma unroll
            for (int i = 0; i < 4; i++)
#pragma unroll
                for (int j = 0; j < 4; j++) {
                    float x = a0[i][j] + a1[i][j];
                    float t = sum[i][j] + x;
                    float e = (sum[i][j] - t) + x;
                    comp[i][j] += e;
                    sum[i][j] = t;
                }
            __syncthreads();
        }
#pragma unroll
        for (int j = 0; j < 4; j++) {
            int gt = t0 + colg * 4 + j;
            float bw = (gt < VTZ) ? g_bwd[gt] : 0.f;
#pragma unroll
            for (int i = 0; i < 4; i++) {
                float sim = sum[i][j] + comp[i][j];
                U[(rowg * 4 + i) * 260 + colg * 4 + j] = 2.f * sim - bw;
            }
        }
        __syncthreads();
#pragma unroll
        for (int c = 0; c < 16; c++) {
            int gt = t0 + scol0 + c;
            if (gt < VTZ) {
                float v = U[srow * 260 + scol0 + c];
                if (v > tv[TOPK - 1]) {
                    int id = gt;
#pragma unroll
                    for (int i = 0; i < TOPK; i++) {
                        if (v > tv[i]) {
                            float t = tv[i]; tv[i] = v; v = t;
                            int tt = ti[i]; ti[i] = id; id = tt;
                        }
                    }
                }
            }
        }
        __syncthreads();
    }
    float* cv = U;
    int* ci = (int*)(U + 16 * 160);
    const int part = tid & 15;
#pragma unroll
    for (int i = 0; i < TOPK; i++) {
        cv[srow * 160 + part * 10 + i] = tv[i];
        ci[srow * 160 + part * 10 + i] = ti[i];
    }
    __syncthreads();
    if (tid < 16) {
        float* v = cv + tid * 160;
        int* id = ci + tid * 160;
        int b = b0 + tid;
        for (int j = 0; j < TOPK; j++) {
            float mx = -3.0e38f;
            int mi = -1, midx = 0x7fffffff;
            for (int i = 0; i < 160; i++) {
                float vv = v[i];
                int vi = id[i];
                if (vv > mx || (vv == mx && vi < midx)) { mx = vv; mi = i; midx = vi; }
            }
            out[b * TOPK + j] = (float)midx;
            v[mi] = -3.0e38f;
        }
    }
}

// ---------------- launch ----------------
extern "C" void kernel_launch(void* const* d_in, const int* in_sizes, int n_in,
                              void* d_out, int out_size) {
    const int* sid;
    const int* cid;
    const float *sst, *stt, *cst, *ctt, *W1, *b1, *W2, *b2, *W3, *b3, *W4, *b4, *w1, *w2;

    long s0 = (n_in >= 16) ? (long)in_sizes[0] : 0;
    bool alphabetical = (s0 == 307200L) || (s0 == 307200L * 4L);

    if (alphabetical) {
        W1 = (const float*)d_in[0];  W2 = (const float*)d_in[1];
        W3 = (const float*)d_in[2];  W4 = (const float*)d_in[3];
        b1 = (const float*)d_in[4];  b2 = (const float*)d_in[5];
        b3 = (const float*)d_in[6];  b4 = (const float*)d_in[7];
        cid = (const int*)d_in[8];
        cst = (const float*)d_in[9];
        ctt = (const float*)d_in[10];
        sid = (const int*)d_in[11];
        sst = (const float*)d_in[12];
        stt = (const float*)d_in[13];
        w1 = (const float*)d_in[14]; w2 = (const float*)d_in[15];
    } else {
        sid = (const int*)d_in[0];
        cid = (const int*)d_in[1];
        sst = (const float*)d_in[2];
        stt = (const float*)d_in[3];
        cst = (const float*)d_in[4];
        ctt = (const float*)d_in[5];
        W1 = (const float*)d_in[6];  b1 = (const float*)d_in[7];
        W2 = (const float*)d_in[8];  b2 = (const float*)d_in[9];
        W3 = (const float*)d_in[10]; b3 = (const float*)d_in[11];
        W4 = (const float*)d_in[12]; b4 = (const float*)d_in[13];
        w1 = (const float*)d_in[14]; w2 = (const float*)d_in[15];
    }
    float* out = (float*)d_out;

    cudaFuncSetAttribute(bwd_kernel, cudaFuncAttributeMaxDynamicSharedMemorySize, BWD_SMEM);
    cudaFuncSetAttribute(gemm_tanh2_kernel, cudaFuncAttributeMaxDynamicSharedMemorySize, GEMM_SMEM);

    // canary FIRST
    fallback_fill_kernel<<<(BQN * TOPK + 255) / 256, 256>>>(out, BQN * TOPK);

    dim3 gg2((DSD + 127) / 128, (VSZ + 63) / 64);  // (3, 313)

    // source-context MLP
    gemm_tanh2_kernel<<<gg2, 128, GEMM_SMEM>>>(cst, 0, W1, b1, 0, VSZ, DSD, DCD, DCD);
    gemm_tanh2_kernel<<<gg2, 128, GEMM_SMEM>>>(nullptr, 1, W3, b3, 1, VSZ, DSD, DSD, DSD);
    l2rows_kernel<<<VSZ, 128>>>(nullptr, 0, VSZ);
    colmean_kernel<<<DSD, 128>>>(0, VSZ, 1.0f / VSZ);
    combine_kernel<<<VSZ, 128>>>(sst, nullptr, 0, w1, 0, VSZ);

    // query path
    l2rows_kernel<<<BQN, 128>>>(cid, 1, BQN);
    colmean_kernel<<<DSD, 128>>>(1, BQN, 1.0f / BQN);
    combine_kernel<<<BQN, 128>>>(sst, sid, 1, w1, 2, BQN);

    // target-context MLP
    gemm_tanh2_kernel<<<gg2, 128, GEMM_SMEM>>>(ctt, 0, W2, b2, 0, VTZ, DSD, DCD, DCD);
    gemm_tanh2_kernel<<<gg2, 128, GEMM_SMEM>>>(nullptr, 1, W4, b4, 1, VTZ, DSD, DSD, DSD);
    l2rows_kernel<<<VTZ, 128>>>(nullptr, 0, VTZ);
    colmean_kernel<<<DSD, 128>>>(0, VTZ, 1.0f / VTZ);
    combine_kernel<<<VTZ, 128>>>(stt, nullptr, 0, w2, 1, VTZ);

    // backward CSLS term (v5: conflict-free B reads)
    bwd_kernel<<<(VTZ + 63) / 64, 128, BWD_SMEM>>>();

    // final scores + top-k indices
    final_kernel<<<BQN / 16, 256>>>(out);
}